// round 10
// baseline (speedup 1.0000x reference)
#include <cuda_runtime.h>
#include <cuda_bf16.h>
#include <math.h>
#include <stdint.h>

#define B_ 8192
#define D_ 4096
#define E_ 512
#define MARGIN 3.0f

// ---------------- scratch (device globals; no cudaMalloc allowed) ----------
__device__ __align__(16) __nv_bfloat16 g_Cb[(size_t)E_ * D_];   // 4MB
__device__ float  g_norm[E_];        // exact fp32 ||e||^2
__device__ float  g_rowdist[B_];     // chosen ||e||^2 - 2*dot (approx or exact)
__device__ double g_xsum;            // sum over all x^2
__device__ int    g_idx[B_];
// per-(row, N-tile) partial argmin results (4 N-tiles of 128 codes)
__device__ float  g_pbestd[B_ * 4];
__device__ int    g_pbesti[B_ * 4];
__device__ int    g_pcnt[B_ * 4];
__device__ int    g_pcand[B_ * 4][4];
__device__ float  g_pdist[B_ * 4][4];
__device__ int    g_hist[E_];

// ---------------- PTX helpers ----------------------------------------------
__device__ __forceinline__ uint32_t smem_u32(const void* p) {
    uint32_t a;
    asm("{ .reg .u64 t; cvta.to.shared.u64 t, %1; cvt.u32.u64 %0, t; }" : "=r"(a) : "l"(p));
    return a;
}
__device__ __forceinline__ void cp16(uint32_t dst, const void* src) {
    asm volatile("cp.async.cg.shared.global [%0], [%1], 16;" :: "r"(dst), "l"(src) : "memory");
}
__device__ __forceinline__ void ldmx4(uint32_t* f, uint32_t addr) {
    asm volatile("ldmatrix.sync.aligned.m8n8.x4.shared.b16 {%0,%1,%2,%3}, [%4];"
                 : "=r"(f[0]), "=r"(f[1]), "=r"(f[2]), "=r"(f[3]) : "r"(addr));
}
__device__ __forceinline__ void mma16816(float* c, const uint32_t* a,
                                         uint32_t b0, uint32_t b1) {
    asm volatile(
        "mma.sync.aligned.m16n8k16.row.col.f32.bf16.bf16.f32 "
        "{%0,%1,%2,%3}, {%4,%5,%6,%7}, {%8,%9}, {%0,%1,%2,%3};"
        : "+f"(c[0]), "+f"(c[1]), "+f"(c[2]), "+f"(c[3])
        : "r"(a[0]), "r"(a[1]), "r"(a[2]), "r"(a[3]), "r"(b0), "r"(b1));
}
__device__ __forceinline__ uint32_t pack_bf2(float lo, float hi) {
    __nv_bfloat162 p = __float22bfloat162_rn(make_float2(lo, hi));
    return ((uint32_t)__bfloat16_as_ushort(p.y) << 16) | __bfloat16_as_ushort(p.x);
}

// ---------------- small kernels ---------------------------------------------
__global__ void k_init() {
    int i = blockIdx.x * 256 + threadIdx.x;          // 8192 threads
    if (i < E_) g_hist[i] = 0;
    for (int r = i; r < B_ * 4; r += 8192) g_pcnt[r] = 0;
    if (i == 0) g_xsum = 0.0;
}

// codebook: exact fp32 norms + bf16 copy
__global__ __launch_bounds__(256) void k_normsC(const float* __restrict__ cb) {
    int e = blockIdx.x;
    const float* row = cb + (size_t)e * D_;
    __nv_bfloat16* brow = g_Cb + (size_t)e * D_;
    float s = 0.f;
    for (int d = threadIdx.x; d < D_; d += 256) {
        float v = row[d];
        s += v * v;
        brow[d] = __float2bfloat16_rn(v);
    }
    __shared__ float sh[256];
    sh[threadIdx.x] = s;
    __syncthreads();
    for (int st = 128; st > 0; st >>= 1) {
        if (threadIdx.x < st) sh[threadIdx.x] += sh[threadIdx.x + st];
        __syncthreads();
    }
    if (threadIdx.x == 0) g_norm[e] = sh[0];
}

// ---------------- mma.sync bf16 GEMM + fused per-tile argmin ----------------
// CTA tile 128x128, BK=64, 8 warps (2x4) each 64x32.
// A: fp32 ldg.128 prefetch -> cvt -> STS bf16, 2 stages. B: cp.async, 3 stages.
// SMEM: A0=0, A1=16K, B0=32K..80K (3x16KB); cns fp32[128] at 80K.
// Epilogue reuses [0,67584) as dist[128][132] fp32.
#define BK 64
#define SOFF_A0 0
#define SOFF_A1 16384
#define SOFF_B0 32768
#define SOFF_CN 81920
#define SMEM_GEMM 82432

__global__ __launch_bounds__(256, 2) void k_gemm_mma(const float* __restrict__ X) {
    extern __shared__ char smem[];
    uint32_t sb = smem_u32(smem);
    float* cns = (float*)(smem + SOFF_CN);
    int tid = threadIdx.x, wid = tid >> 5, lane = tid & 31;
    int n0 = blockIdx.x * 128, m0 = blockIdx.y * 128;
    int wm = (wid >> 2) * 64, wn = (wid & 3) * 32;

    const float* gA = X + (size_t)m0 * D_;
    const __nv_bfloat16* gB = g_Cb + (size_t)n0 * D_;
    for (int i = tid; i < 128; i += 256) cns[i] = g_norm[n0 + i];

    const int r0 = tid >> 3, u = tid & 7;
    const uint32_t swz = (uint32_t)((u ^ (r0 & 7)) << 4);
    const bool do_x2 = (blockIdx.x == 0);
    float x2 = 0.f;

    float4 pa[8];

    auto ldgA = [&](int kt) {
#pragma unroll
        for (int i = 0; i < 4; i++) {
            const float* s = gA + (size_t)(r0 + 32 * i) * D_ + kt * BK + u * 8;
            pa[2 * i]     = *reinterpret_cast<const float4*>(s);
            pa[2 * i + 1] = *reinterpret_cast<const float4*>(s + 4);
        }
    };
    auto stsA = [&](uint32_t aoff) {
#pragma unroll
        for (int i = 0; i < 4; i++) {
            float4 a = pa[2 * i], b = pa[2 * i + 1];
            uint4 v;
            v.x = pack_bf2(a.x, a.y);
            v.y = pack_bf2(a.z, a.w);
            v.z = pack_bf2(b.x, b.y);
            v.w = pack_bf2(b.z, b.w);
            *reinterpret_cast<uint4*>(smem + aoff + (uint32_t)(r0 + 32 * i) * 128 + swz) = v;
            if (do_x2)
                x2 += a.x * a.x + a.y * a.y + a.z * a.z + a.w * a.w
                    + b.x * b.x + b.y * b.y + b.z * b.z + b.w * b.w;
        }
    };
    auto ldB = [&](int kt, uint32_t boff) {
#pragma unroll
        for (int i = 0; i < 4; i++)
            cp16(sb + boff + (uint32_t)(r0 + 32 * i) * 128 + swz,
                 gB + (size_t)(r0 + 32 * i) * D_ + kt * BK + u * 8);
    };

    int arow[4], brow[2];
#pragma unroll
    for (int mi = 0; mi < 4; mi++)
        arow[mi] = wm + 16 * mi + (lane & 7) + 8 * ((lane >> 3) & 1);
#pragma unroll
    for (int p = 0; p < 2; p++)
        brow[p] = wn + 16 * p + (lane & 7) + 8 * ((lane >> 4) & 1);
    const int au = (lane >> 4) & 1, bu = (lane >> 3) & 1;

    float acc[4][4][4];
#pragma unroll
    for (int a = 0; a < 4; a++)
#pragma unroll
        for (int b = 0; b < 4; b++)
#pragma unroll
            for (int c = 0; c < 4; c++) acc[a][b][c] = 0.f;

    // prologue
    ldgA(0);
    stsA(SOFF_A0);
    ldgA(1);
    ldB(0, SOFF_B0);
    asm volatile("cp.async.commit_group;" ::: "memory");
    ldB(1, SOFF_B0 + 16384);
    asm volatile("cp.async.commit_group;" ::: "memory");

    const int NKT = D_ / BK;      // 64
    for (int kt = 0; kt < NKT; kt++) {
        if (kt < NKT - 1) {
            asm volatile("cp.async.wait_group 1;" ::: "memory");
        } else {
            asm volatile("cp.async.wait_group 0;" ::: "memory");
        }
        __syncthreads();
        if (kt + 2 < NKT) {
            ldB(kt + 2, SOFF_B0 + (uint32_t)((kt + 2) % 3) * 16384);
            asm volatile("cp.async.commit_group;" ::: "memory");
        }

        uint32_t as = sb + ((kt & 1) ? SOFF_A1 : SOFF_A0);
        uint32_t bs = sb + SOFF_B0 + (uint32_t)(kt % 3) * 16384;

#pragma unroll
        for (int ks = 0; ks < 4; ks++) {
            uint32_t af[4][4], bf[2][4];
#pragma unroll
            for (int mi = 0; mi < 4; mi++) {
                int r = arow[mi], uu = ks * 2 + au;
                ldmx4(af[mi], as + r * 128 + ((uu ^ (r & 7)) << 4));
            }
#pragma unroll
            for (int p = 0; p < 2; p++) {
                int r = brow[p], uu = ks * 2 + bu;
                ldmx4(bf[p], bs + r * 128 + ((uu ^ (r & 7)) << 4));
            }
#pragma unroll
            for (int mi = 0; mi < 4; mi++)
#pragma unroll
                for (int p = 0; p < 2; p++) {
                    mma16816(acc[mi][2 * p],     af[mi], bf[p][0], bf[p][1]);
                    mma16816(acc[mi][2 * p + 1], af[mi], bf[p][2], bf[p][3]);
                }
        }

        if (kt + 1 < NKT) stsA((kt & 1) ? SOFF_A0 : SOFF_A1);
        if (kt + 2 < NKT) ldgA(kt + 2);
    }

    // ---- fused epilogue ----------------------------------------------------
    __syncthreads();            // all warps done reading pipeline smem
    float* ds = (float*)smem;   // dist[128][132]
    int gid = lane >> 2, tig = lane & 3;
#pragma unroll
    for (int mi = 0; mi < 4; mi++) {
        int r1 = wm + 16 * mi + gid;
#pragma unroll
        for (int nj = 0; nj < 4; nj++) {
            int c = wn + 8 * nj + 2 * tig;
            float cn0 = cns[c], cn1 = cns[c + 1];
            ds[r1 * 132 + c]           = cn0 - 2.f * acc[mi][nj][0];
            ds[r1 * 132 + c + 1]       = cn1 - 2.f * acc[mi][nj][1];
            ds[(r1 + 8) * 132 + c]     = cn0 - 2.f * acc[mi][nj][2];
            ds[(r1 + 8) * 132 + c + 1] = cn1 - 2.f * acc[mi][nj][3];
        }
    }
    if (do_x2) {
#pragma unroll
        for (int off = 16; off > 0; off >>= 1)
            x2 += __shfl_xor_sync(0xffffffffu, x2, off);
        if (lane == 0) ((float*)(smem + 67584))[wid] = x2;
    }
    __syncthreads();
    if (do_x2 && tid == 0) {
        float s = 0.f;
        const float* red = (const float*)(smem + 67584);
        for (int w = 0; w < 8; w++) s += red[w];
        atomicAdd(&g_xsum, (double)s);
    }

    // per-row min + margin candidates: 2 threads per row, 64 cols each
    {
        int r = tid >> 1, half = tid & 1;
        const float* rowp = ds + r * 132 + half * 64;
        float best = INFINITY;
        int bidx = 1 << 30;
#pragma unroll
        for (int i = 0; i < 16; i++) {
            float4 v = *reinterpret_cast<const float4*>(rowp + 4 * i);
            const float* f = reinterpret_cast<const float*>(&v);
#pragma unroll
            for (int e = 0; e < 4; e++) {
                int c = half * 64 + 4 * i + e;
                if (f[e] < best) { best = f[e]; bidx = c; }   // ascending c
            }
        }
        float ov = __shfl_xor_sync(0xffffffffu, best, 1);
        int   oi = __shfl_xor_sync(0xffffffffu, bidx, 1);
        if (ov < best || (ov == best && oi < bidx)) { best = ov; bidx = oi; }

        int prow = (m0 + r) * 4 + blockIdx.x;
        if (half == 0) { g_pbestd[prow] = best; g_pbesti[prow] = n0 + bidx; }
        float thr = best + MARGIN;
#pragma unroll
        for (int i = 0; i < 16; i++) {
            float4 v = *reinterpret_cast<const float4*>(rowp + 4 * i);
            const float* f = reinterpret_cast<const float*>(&v);
#pragma unroll
            for (int e = 0; e < 4; e++) {
                if (f[e] <= thr) {
                    int p = atomicAdd(&g_pcnt[prow], 1);
                    if (p < 4) {
                        g_pcand[prow][p] = n0 + half * 64 + 4 * i + e;
                        g_pdist[prow][p] = f[e];
                    }
                }
            }
        }
    }
}

// ---------------- combine partials + exact fp32 rescore ----------------------
__global__ __launch_bounds__(128) void k_rescore(const float* __restrict__ X,
                                                 const float* __restrict__ Cb) {
    __shared__ float sdist[16];
    __shared__ int   sidx[16];
    __shared__ int   scnt;        // -1 = overflow -> full scan
    __shared__ float sgbest;
    __shared__ int   sgbi;
    int b = blockIdx.x;
    int t = threadIdx.x;

    if (t == 0) {
        float gbest = INFINITY;
        int gbi = 1 << 30;
        bool full = false;
#pragma unroll
        for (int ct = 0; ct < 4; ct++) {
            float d = g_pbestd[b * 4 + ct];
            int i = g_pbesti[b * 4 + ct];
            if (d < gbest || (d == gbest && i < gbi)) { gbest = d; gbi = i; }
        }
        float thr = gbest + MARGIN;
        int cnt = 0;
#pragma unroll
        for (int ct = 0; ct < 4; ct++) {
            int n = g_pcnt[b * 4 + ct];
            if (n > 4) { full = true; break; }
            for (int k = 0; k < n; k++) {
                float d = g_pdist[b * 4 + ct][k];
                if (d <= thr) { sdist[cnt] = d; sidx[cnt] = g_pcand[b * 4 + ct][k]; cnt++; }
            }
        }
        scnt = full ? -1 : cnt;
        sgbest = gbest;
        sgbi = gbi;
    }
    __syncthreads();
    int cnt = scnt;
    if (cnt >= 0 && cnt <= 1) {
        if (t == 0) { g_idx[b] = sgbi; g_rowdist[b] = sgbest; }
        return;
    }

    __shared__ float sh[128];
    const float4* x4 = reinterpret_cast<const float4*>(X + (size_t)b * D_);
    int total = (cnt > 0) ? cnt : E_;
    float bestd = INFINITY;
    int besti = 1 << 30;
    for (int c = 0; c < total; c++) {
        int e = (cnt > 0) ? sidx[c] : c;
        const float4* c4 = reinterpret_cast<const float4*>(Cb + (size_t)e * D_);
        float s = 0.f;
        for (int i = t; i < D_ / 4; i += 128) {
            float4 xv = x4[i], cv = c4[i];
            s += xv.x * cv.x + xv.y * cv.y + xv.z * cv.z + xv.w * cv.w;
        }
        sh[t] = s;
        __syncthreads();
        for (int st = 64; st > 0; st >>= 1) {
            if (t < st) sh[t] += sh[t + st];
            __syncthreads();
        }
        float d = g_norm[e] - 2.f * sh[0];
        if (d < bestd || (d == bestd && e < besti)) { bestd = d; besti = e; }
        __syncthreads();
    }
    if (t == 0) { g_idx[b] = besti; g_rowdist[b] = bestd; }
}

// ---------------- outputs (no X read; quantized_st == codebook row) ----------
__global__ __launch_bounds__(512) void k_out(const float* __restrict__ Cb,
                                             float* __restrict__ outQ,
                                             float* __restrict__ outEnc) {
    __shared__ float qs[D_];
    int b = blockIdx.x;
    int t = threadIdx.x;
    int idx = g_idx[b];

    if (t == 0) atomicAdd(&g_hist[idx], 1);

    if (t < 256) {
        float2 e2;
        int c = 2 * t;
        e2.x = (c == idx) ? 1.f : 0.f;
        e2.y = (c + 1 == idx) ? 1.f : 0.f;
        reinterpret_cast<float2*>(outEnc + (size_t)b * E_)[t] = e2;
    }

    const float4* c4 = reinterpret_cast<const float4*>(Cb + (size_t)idx * D_);
    float4* q4 = reinterpret_cast<float4*>(qs);
#pragma unroll
    for (int i = 0; i < 2; i++) q4[t + 512 * i] = c4[t + 512 * i];
    __syncthreads();

    float* o = outQ + (size_t)b * D_;
    if (t < 3) o[t] = qs[t];
    if (t == 3) o[4095] = qs[4095];
    for (int i = t; i < 1023; i += 512) {
        int j = 3 + 4 * i;
        float4 v = make_float4(qs[j], qs[j + 1], qs[j + 2], qs[j + 3]);
        *reinterpret_cast<float4*>(o + j) = v;
    }
}

// ---------------- finalize: loss from row distances + perplexity -------------
__global__ __launch_bounds__(512) void k_final(float* __restrict__ out) {
    __shared__ double sh[512];
    int t = threadIdx.x;

    double s = 0.0;
    for (int i = t; i < B_; i += 512)
        s += (double)g_rowdist[i];
    sh[t] = s;
    __syncthreads();
    for (int st = 256; st > 0; st >>= 1) {
        if (t < st) sh[t] += sh[t + st];
        __syncthreads();
    }
    double lsum = sh[0] + g_xsum;
    __syncthreads();

    double p = (double)g_hist[t] / (double)B_;
    sh[t] = p * log(p + 1e-10);
    __syncthreads();
    for (int st = 256; st > 0; st >>= 1) {
        if (t < st) sh[t] += sh[t + st];
        __syncthreads();
    }
    if (t == 0) {
        double mse = lsum / ((double)B_ * (double)D_);
        out[0] = (float)(1.25 * mse);
        out[1 + (size_t)B_ * D_] = (float)exp(-sh[0]);
    }
}

// ---------------------------------------------------------------------------
extern "C" void kernel_launch(void* const* d_in, const int* in_sizes, int n_in,
                              void* d_out, int out_size) {
    (void)in_sizes; (void)n_in; (void)out_size;
    const float* X  = (const float*)d_in[0];
    const float* Cb = (const float*)d_in[1];
    float* out = (float*)d_out;

    float* outQ   = out + 1;
    float* outEnc = out + 2 + (size_t)B_ * D_;

    cudaFuncSetAttribute(k_gemm_mma, cudaFuncAttributeMaxDynamicSharedMemorySize,
                         SMEM_GEMM);

    k_init<<<32, 256>>>();
    k_normsC<<<E_, 256>>>(Cb);
    dim3 gg(E_ / 128, B_ / 128);
    k_gemm_mma<<<gg, 256, SMEM_GEMM>>>(X);
    k_rescore<<<B_, 128>>>(X, Cb);
    k_out<<<B_, 512>>>(Cb, outQ, outEnc);
    k_final<<<1, 512>>>(out);
}

// round 14
// speedup vs baseline: 1.0208x; 1.0208x over previous
#include <cuda_runtime.h>
#include <cuda_bf16.h>
#include <math.h>
#include <stdint.h>

#define B_ 8192
#define D_ 4096
#define E_ 512
#define MARGIN 3.0f

// ---------------- scratch (device globals; no cudaMalloc allowed) ----------
__device__ __align__(16) __nv_bfloat16 g_Cb[(size_t)E_ * D_];   // 4MB
__device__ float  g_norm[E_];        // exact fp32 ||e||^2
__device__ float  g_rowdist[B_];     // chosen ||e||^2 - 2*dot (approx or exact)
__device__ double g_xsum;            // sum over all x^2
__device__ int    g_idx[B_];
// per-(row, N-tile) partial argmin results (4 N-tiles of 128 codes)
__device__ float  g_pbestd[B_ * 4];
__device__ int    g_pbesti[B_ * 4];
__device__ int    g_pcnt[B_ * 4];
__device__ int    g_pcand[B_ * 4][4];
__device__ float  g_pdist[B_ * 4][4];
// worklist of ambiguous rows
__device__ int    g_nwork;
__device__ int    g_wrow[B_];
__device__ int    g_wcnt[B_];        // 0 = full scan, else #candidates
__device__ int    g_wcand[B_][16];
__device__ int    g_hist[E_];

// ---------------- PTX helpers ----------------------------------------------
__device__ __forceinline__ uint32_t smem_u32(const void* p) {
    uint32_t a;
    asm("{ .reg .u64 t; cvta.to.shared.u64 t, %1; cvt.u32.u64 %0, t; }" : "=r"(a) : "l"(p));
    return a;
}
__device__ __forceinline__ void cp16(uint32_t dst, const void* src) {
    asm volatile("cp.async.cg.shared.global [%0], [%1], 16;" :: "r"(dst), "l"(src) : "memory");
}
__device__ __forceinline__ void ldmx4(uint32_t* f, uint32_t addr) {
    asm volatile("ldmatrix.sync.aligned.m8n8.x4.shared.b16 {%0,%1,%2,%3}, [%4];"
                 : "=r"(f[0]), "=r"(f[1]), "=r"(f[2]), "=r"(f[3]) : "r"(addr));
}
__device__ __forceinline__ void mma16816(float* c, const uint32_t* a,
                                         uint32_t b0, uint32_t b1) {
    asm volatile(
        "mma.sync.aligned.m16n8k16.row.col.f32.bf16.bf16.f32 "
        "{%0,%1,%2,%3}, {%4,%5,%6,%7}, {%8,%9}, {%0,%1,%2,%3};"
        : "+f"(c[0]), "+f"(c[1]), "+f"(c[2]), "+f"(c[3])
        : "r"(a[0]), "r"(a[1]), "r"(a[2]), "r"(a[3]), "r"(b0), "r"(b1));
}
__device__ __forceinline__ uint32_t pack_bf2(float lo, float hi) {
    __nv_bfloat162 p = __float22bfloat162_rn(make_float2(lo, hi));
    return ((uint32_t)__bfloat16_as_ushort(p.y) << 16) | __bfloat16_as_ushort(p.x);
}

// ---------------- small kernels ---------------------------------------------
__global__ void k_init() {
    int i = blockIdx.x * 256 + threadIdx.x;          // 8192 threads
    if (i < E_) g_hist[i] = 0;
    for (int r = i; r < B_ * 4; r += 8192) g_pcnt[r] = 0;
    if (i == 0) { g_xsum = 0.0; g_nwork = 0; }
}

// codebook: exact fp32 norms + bf16 copy
__global__ __launch_bounds__(256) void k_normsC(const float* __restrict__ cb) {
    int e = blockIdx.x;
    const float* row = cb + (size_t)e * D_;
    __nv_bfloat16* brow = g_Cb + (size_t)e * D_;
    float s = 0.f;
    for (int d = threadIdx.x; d < D_; d += 256) {
        float v = row[d];
        s += v * v;
        brow[d] = __float2bfloat16_rn(v);
    }
    __shared__ float sh[256];
    sh[threadIdx.x] = s;
    __syncthreads();
    for (int st = 128; st > 0; st >>= 1) {
        if (threadIdx.x < st) sh[threadIdx.x] += sh[threadIdx.x + st];
        __syncthreads();
    }
    if (threadIdx.x == 0) g_norm[e] = sh[0];
}

// ---------------- mma.sync bf16 GEMM + fused per-tile argmin ----------------
#define BK 64
#define SOFF_A0 0
#define SOFF_A1 16384
#define SOFF_B0 32768
#define SOFF_CN 81920
#define SMEM_GEMM 82432

__global__ __launch_bounds__(256, 2) void k_gemm_mma(const float* __restrict__ X) {
    extern __shared__ char smem[];
    uint32_t sb = smem_u32(smem);
    float* cns = (float*)(smem + SOFF_CN);
    int tid = threadIdx.x, wid = tid >> 5, lane = tid & 31;
    int n0 = blockIdx.x * 128, m0 = blockIdx.y * 128;
    int wm = (wid >> 2) * 64, wn = (wid & 3) * 32;

    const float* gA = X + (size_t)m0 * D_;
    const __nv_bfloat16* gB = g_Cb + (size_t)n0 * D_;
    for (int i = tid; i < 128; i += 256) cns[i] = g_norm[n0 + i];

    const int r0 = tid >> 3, u = tid & 7;
    const uint32_t swz = (uint32_t)((u ^ (r0 & 7)) << 4);
    const bool do_x2 = (blockIdx.x == 0);
    float x2 = 0.f;

    float4 pa[8];

    auto ldgA = [&](int kt) {
#pragma unroll
        for (int i = 0; i < 4; i++) {
            const float* s = gA + (size_t)(r0 + 32 * i) * D_ + kt * BK + u * 8;
            pa[2 * i]     = *reinterpret_cast<const float4*>(s);
            pa[2 * i + 1] = *reinterpret_cast<const float4*>(s + 4);
        }
    };
    auto stsA = [&](uint32_t aoff) {
#pragma unroll
        for (int i = 0; i < 4; i++) {
            float4 a = pa[2 * i], b = pa[2 * i + 1];
            uint4 v;
            v.x = pack_bf2(a.x, a.y);
            v.y = pack_bf2(a.z, a.w);
            v.z = pack_bf2(b.x, b.y);
            v.w = pack_bf2(b.z, b.w);
            *reinterpret_cast<uint4*>(smem + aoff + (uint32_t)(r0 + 32 * i) * 128 + swz) = v;
            if (do_x2)
                x2 += a.x * a.x + a.y * a.y + a.z * a.z + a.w * a.w
                    + b.x * b.x + b.y * b.y + b.z * b.z + b.w * b.w;
        }
    };
    auto ldB = [&](int kt, uint32_t boff) {
#pragma unroll
        for (int i = 0; i < 4; i++)
            cp16(sb + boff + (uint32_t)(r0 + 32 * i) * 128 + swz,
                 gB + (size_t)(r0 + 32 * i) * D_ + kt * BK + u * 8);
    };

    int arow[4], brow[2];
#pragma unroll
    for (int mi = 0; mi < 4; mi++)
        arow[mi] = wm + 16 * mi + (lane & 7) + 8 * ((lane >> 3) & 1);
#pragma unroll
    for (int p = 0; p < 2; p++)
        brow[p] = wn + 16 * p + (lane & 7) + 8 * ((lane >> 4) & 1);
    const int au = (lane >> 4) & 1, bu = (lane >> 3) & 1;

    float acc[4][4][4];
#pragma unroll
    for (int a = 0; a < 4; a++)
#pragma unroll
        for (int b = 0; b < 4; b++)
#pragma unroll
            for (int c = 0; c < 4; c++) acc[a][b][c] = 0.f;

    // prologue
    ldgA(0);
    stsA(SOFF_A0);
    ldgA(1);
    ldB(0, SOFF_B0);
    asm volatile("cp.async.commit_group;" ::: "memory");
    ldB(1, SOFF_B0 + 16384);
    asm volatile("cp.async.commit_group;" ::: "memory");

    const int NKT = D_ / BK;      // 64
    for (int kt = 0; kt < NKT; kt++) {
        if (kt < NKT - 1) {
            asm volatile("cp.async.wait_group 1;" ::: "memory");
        } else {
            asm volatile("cp.async.wait_group 0;" ::: "memory");
        }
        __syncthreads();
        if (kt + 2 < NKT) {
            ldB(kt + 2, SOFF_B0 + (uint32_t)((kt + 2) % 3) * 16384);
            asm volatile("cp.async.commit_group;" ::: "memory");
        }

        uint32_t as = sb + ((kt & 1) ? SOFF_A1 : SOFF_A0);
        uint32_t bs = sb + SOFF_B0 + (uint32_t)(kt % 3) * 16384;

#pragma unroll
        for (int ks = 0; ks < 4; ks++) {
            uint32_t af[4][4], bf[2][4];
#pragma unroll
            for (int mi = 0; mi < 4; mi++) {
                int r = arow[mi], uu = ks * 2 + au;
                ldmx4(af[mi], as + r * 128 + ((uu ^ (r & 7)) << 4));
            }
#pragma unroll
            for (int p = 0; p < 2; p++) {
                int r = brow[p], uu = ks * 2 + bu;
                ldmx4(bf[p], bs + r * 128 + ((uu ^ (r & 7)) << 4));
            }
#pragma unroll
            for (int mi = 0; mi < 4; mi++)
#pragma unroll
                for (int p = 0; p < 2; p++) {
                    mma16816(acc[mi][2 * p],     af[mi], bf[p][0], bf[p][1]);
                    mma16816(acc[mi][2 * p + 1], af[mi], bf[p][2], bf[p][3]);
                }
        }

        if (kt + 1 < NKT) stsA((kt & 1) ? SOFF_A0 : SOFF_A1);
        if (kt + 2 < NKT) ldgA(kt + 2);
    }

    // ---- fused epilogue ----------------------------------------------------
    __syncthreads();
    float* ds = (float*)smem;   // dist[128][132]
    int gid = lane >> 2, tig = lane & 3;
#pragma unroll
    for (int mi = 0; mi < 4; mi++) {
        int r1 = wm + 16 * mi + gid;
#pragma unroll
        for (int nj = 0; nj < 4; nj++) {
            int c = wn + 8 * nj + 2 * tig;
            float cn0 = cns[c], cn1 = cns[c + 1];
            ds[r1 * 132 + c]           = cn0 - 2.f * acc[mi][nj][0];
            ds[r1 * 132 + c + 1]       = cn1 - 2.f * acc[mi][nj][1];
            ds[(r1 + 8) * 132 + c]     = cn0 - 2.f * acc[mi][nj][2];
            ds[(r1 + 8) * 132 + c + 1] = cn1 - 2.f * acc[mi][nj][3];
        }
    }
    if (do_x2) {
#pragma unroll
        for (int off = 16; off > 0; off >>= 1)
            x2 += __shfl_xor_sync(0xffffffffu, x2, off);
        if (lane == 0) ((float*)(smem + 67584))[wid] = x2;
    }
    __syncthreads();
    if (do_x2 && tid == 0) {
        float s = 0.f;
        const float* red = (const float*)(smem + 67584);
        for (int w = 0; w < 8; w++) s += red[w];
        atomicAdd(&g_xsum, (double)s);
    }

    // per-row min + margin candidates: 2 threads per row, 64 cols each
    {
        int r = tid >> 1, half = tid & 1;
        const float* rowp = ds + r * 132 + half * 64;
        float best = INFINITY;
        int bidx = 1 << 30;
#pragma unroll
        for (int i = 0; i < 16; i++) {
            float4 v = *reinterpret_cast<const float4*>(rowp + 4 * i);
            const float* f = reinterpret_cast<const float*>(&v);
#pragma unroll
            for (int e = 0; e < 4; e++) {
                int c = half * 64 + 4 * i + e;
                if (f[e] < best) { best = f[e]; bidx = c; }
            }
        }
        float ov = __shfl_xor_sync(0xffffffffu, best, 1);
        int   oi = __shfl_xor_sync(0xffffffffu, bidx, 1);
        if (ov < best || (ov == best && oi < bidx)) { best = ov; bidx = oi; }

        int prow = (m0 + r) * 4 + blockIdx.x;
        if (half == 0) { g_pbestd[prow] = best; g_pbesti[prow] = n0 + bidx; }
        float thr = best + MARGIN;
#pragma unroll
        for (int i = 0; i < 16; i++) {
            float4 v = *reinterpret_cast<const float4*>(rowp + 4 * i);
            const float* f = reinterpret_cast<const float*>(&v);
#pragma unroll
            for (int e = 0; e < 4; e++) {
                if (f[e] <= thr) {
                    int p = atomicAdd(&g_pcnt[prow], 1);
                    if (p < 4) {
                        g_pcand[prow][p] = n0 + half * 64 + 4 * i + e;
                        g_pdist[prow][p] = f[e];
                    }
                }
            }
        }
    }
}

// ---------------- combine partials: warp per row, build worklist -------------
__global__ __launch_bounds__(256) void k_combine() {
    int b = (blockIdx.x * 256 + threadIdx.x) >> 5;
    int lane = threadIdx.x & 31;
    if (b >= B_) return;

    float best = INFINITY;
    int bidx = 1 << 30;
    int mycnt = 0;
    if (lane < 4) {
        best = g_pbestd[b * 4 + lane];
        bidx = g_pbesti[b * 4 + lane];
        mycnt = g_pcnt[b * 4 + lane];
    }
#pragma unroll
    for (int off = 16; off > 0; off >>= 1) {
        float ov = __shfl_xor_sync(0xffffffffu, best, off);
        int   oi = __shfl_xor_sync(0xffffffffu, bidx, off);
        if (ov < best || (ov == best && oi < bidx)) { best = ov; bidx = oi; }
    }
    bool ovf = __any_sync(0xffffffffu, mycnt > 4);
    float thr = best + MARGIN;

    int lc = 0;
    if (lane < 4 && !ovf)
        for (int k = 0; k < mycnt; k++)
            if (g_pdist[b * 4 + lane][k] <= thr) lc++;
#pragma unroll
    for (int off = 16; off > 0; off >>= 1)
        lc += __shfl_xor_sync(0xffffffffu, lc, off);

    if (!ovf && lc <= 1) {
        if (lane == 0) { g_idx[b] = bidx; g_rowdist[b] = best; }
        return;
    }
    if (lane == 0) {
        int slot = atomicAdd(&g_nwork, 1);
        g_wrow[slot] = b;
        if (ovf) {
            g_wcnt[slot] = 0;     // full scan
        } else {
            int c = 0;
            for (int ct = 0; ct < 4; ct++) {
                int n = g_pcnt[b * 4 + ct];
                for (int k = 0; k < n; k++)
                    if (g_pdist[b * 4 + ct][k] <= thr)
                        g_wcand[slot][c++] = g_pcand[b * 4 + ct][k];
            }
            g_wcnt[slot] = c;
        }
    }
}

// ---------------- exact fp32 rescore of worklist rows ------------------------
__global__ __launch_bounds__(128) void k_rescore(const float* __restrict__ X,
                                                 const float* __restrict__ Cb) {
    __shared__ float sh[128];
    int t = threadIdx.x;
    int nw = g_nwork;
    for (int w = blockIdx.x; w < nw; w += gridDim.x) {
        int b = g_wrow[w];
        int cnt = g_wcnt[w];
        const float4* x4 = reinterpret_cast<const float4*>(X + (size_t)b * D_);
        int total = (cnt > 0) ? cnt : E_;
        float bestd = INFINITY;
        int besti = 1 << 30;
        for (int c = 0; c < total; c++) {
            int e = (cnt > 0) ? g_wcand[w][c] : c;
            const float4* c4 = reinterpret_cast<const float4*>(Cb + (size_t)e * D_);
            float s = 0.f;
            for (int i = t; i < D_ / 4; i += 128) {
                float4 xv = x4[i], cv = c4[i];
                s += xv.x * cv.x + xv.y * cv.y + xv.z * cv.z + xv.w * cv.w;
            }
            sh[t] = s;
            __syncthreads();
            for (int st = 64; st > 0; st >>= 1) {
                if (t < st) sh[t] += sh[t + st];
                __syncthreads();
            }
            float d = g_norm[e] - 2.f * sh[0];
            if (d < bestd || (d == bestd && e < besti)) { bestd = d; besti = e; }
            __syncthreads();
        }
        if (t == 0) { g_idx[b] = besti; g_rowdist[b] = bestd; }
        __syncthreads();
    }
}

// ---------------- outputs (no X read; quantized_st == codebook row) ----------
__global__ __launch_bounds__(512) void k_out(const float* __restrict__ Cb,
                                             float* __restrict__ outQ,
                                             float* __restrict__ outEnc) {
    __shared__ float qs[D_];
    int b = blockIdx.x;
    int t = threadIdx.x;
    int idx = g_idx[b];

    if (t == 0) atomicAdd(&g_hist[idx], 1);

    if (t < 256) {
        float2 e2;
        int c = 2 * t;
        e2.x = (c == idx) ? 1.f : 0.f;
        e2.y = (c + 1 == idx) ? 1.f : 0.f;
        reinterpret_cast<float2*>(outEnc + (size_t)b * E_)[t] = e2;
    }

    const float4* c4 = reinterpret_cast<const float4*>(Cb + (size_t)idx * D_);
    float4* q4 = reinterpret_cast<float4*>(qs);
#pragma unroll
    for (int i = 0; i < 2; i++) q4[t + 512 * i] = c4[t + 512 * i];
    __syncthreads();

    float* o = outQ + (size_t)b * D_;
    if (t < 3) o[t] = qs[t];
    if (t == 3) o[4095] = qs[4095];
    for (int i = t; i < 1023; i += 512) {
        int j = 3 + 4 * i;
        float4 v = make_float4(qs[j], qs[j + 1], qs[j + 2], qs[j + 3]);
        *reinterpret_cast<float4*>(o + j) = v;
    }
}

// ---------------- finalize: loss from row distances + perplexity -------------
__global__ __launch_bounds__(512) void k_final(float* __restrict__ out) {
    __shared__ double sh[512];
    int t = threadIdx.x;

    double s = 0.0;
    for (int i = t; i < B_; i += 512)
        s += (double)g_rowdist[i];
    sh[t] = s;
    __syncthreads();
    for (int st = 256; st > 0; st >>= 1) {
        if (t < st) sh[t] += sh[t + st];
        __syncthreads();
    }
    double lsum = sh[0] + g_xsum;
    __syncthreads();

    double p = (double)g_hist[t] / (double)B_;
    sh[t] = p * log(p + 1e-10);
    __syncthreads();
    for (int st = 256; st > 0; st >>= 1) {
        if (t < st) sh[t] += sh[t + st];
        __syncthreads();
    }
    if (t == 0) {
        double mse = lsum / ((double)B_ * (double)D_);
        out[0] = (float)(1.25 * mse);
        out[1 + (size_t)B_ * D_] = (float)exp(-sh[0]);
    }
}

// ---------------------------------------------------------------------------
extern "C" void kernel_launch(void* const* d_in, const int* in_sizes, int n_in,
                              void* d_out, int out_size) {
    (void)in_sizes; (void)n_in; (void)out_size;
    const float* X  = (const float*)d_in[0];
    const float* Cb = (const float*)d_in[1];
    float* out = (float*)d_out;

    float* outQ   = out + 1;
    float* outEnc = out + 2 + (size_t)B_ * D_;

    cudaFuncSetAttribute(k_gemm_mma, cudaFuncAttributeMaxDynamicSharedMemorySize,
                         SMEM_GEMM);

    k_init<<<32, 256>>>();
    k_normsC<<<E_, 256>>>(Cb);
    dim3 gg(E_ / 128, B_ / 128);
    k_gemm_mma<<<gg, 256, SMEM_GEMM>>>(X);
    k_combine<<<B_ / 8, 256>>>();
    k_rescore<<<1024, 128>>>(X, Cb);
    k_out<<<B_, 512>>>(Cb, outQ, outEnc);
    k_final<<<1, 512>>>(out);
}